// round 15
// baseline (speedup 1.0000x reference)
#include <cuda_runtime.h>

#define TLEN 256
#define FULLMASK 0xffffffffu

#define OFF_Z   0u
#define OFF_MU  2097152u
#define OFF_SIG 4194304u
#define OFF_A   71303168u
#define OFF_AT  72351744u
#define OFF_BT  139460608u
#define OFF_CT  156237824u

struct SW {
    float4 AmT[1024];      // [k*32+row] = (A0..A3)[row][k]
    float4 CmS[512];       // [flat]
    float4 BmS[256];       // [flat]
    float4 BmT[256];       // [j*32+row]
    float  QT[1024];       // [k*32+row] = Q[row][k]
    float4 Wh4[2048];      // [hh*32+lane] = Wh[hh*192+lane + {0,32,64,96}]
    float2 Wh2[2048];      // [hh*32+lane] = Wh[hh*192+lane + {128,160}]
    float4 Wx4[1024];      // [k*32+lane]  = Wx[k*192+lane + {0,32,64,96}]
    float2 Wx2[1024];      // [k*32+lane]  = Wx[k*192+lane + {128,160}]
    float4 Wo4[64];
    float  bhs[192], bxs[192];
};
struct SC {
    float Ls[32 * 36];     // L rows (float4 pad)
    float Gs[32 * 36];     // G rows
    float As4[32 * 36];    // A_t rows hand-off
    float Ss1[32 * 36];    // helper's S partial (k<16)
    float Cts[32 * 17];    // [c*17+r] = C_t[r][c]
    float gxs[192];        // spine -> helper gate inputs
    float mus[32];         // helper -> spine mu_new
    float alsh[4];
};
struct SAll { SW w; SC c[2]; };

__device__ __forceinline__ float fast_tanh(float x) {
    float y; asm("tanh.approx.f32 %0, %1;" : "=f"(y) : "f"(x)); return y;
}
__device__ __forceinline__ float fast_sigmoid(float x) {
    return 0.5f + 0.5f * fast_tanh(0.5f * x);
}
__device__ __forceinline__ float mix4(float4 v, float a0, float a1, float a2, float a3) {
    return fmaf(v.x, a0, fmaf(v.y, a1, fmaf(v.z, a2, v.w * a3)));
}

// Plain warp Cholesky (init only).
__device__ __forceinline__ void chol_init(float a[32], int lane, float* Ls)
{
#pragma unroll
    for (int j = 0; j < 32; ++j) {
        float d   = __shfl_sync(FULLMASK, a[j], j);
        float rs  = rsqrtf(d);
        float lij = a[j] * rs;
        a[j] = lij;
        float lsq = lij * lij;
#pragma unroll
        for (int k = j + 1; k < 32; ++k) {
            float lkj = __shfl_sync(FULLMASK, lij, k);
            if (k == lane) a[k] -= lsq;
            else           a[k] = fmaf(-lij, lkj, a[k]);
        }
    }
#pragma unroll
    for (int k = 0; k < 32; ++k) if (k > lane) a[k] = 0.f;
#pragma unroll
    for (int i = 0; i < 8; ++i)
        *(float4*)&Ls[lane * 36 + 4 * i] =
            make_float4(a[4*i], a[4*i+1], a[4*i+2], a[4*i+3]);
}

__global__ void __launch_bounds__(128, 1)
lgssm_kernel(const float* __restrict__ mu0,   const float* __restrict__ Sig0,
             const float* __restrict__ alpha0,const float* __restrict__ h0,
             const float* __restrict__ u_f,   const float* __restrict__ eps_g,
             const float* __restrict__ Ab,    const float* __restrict__ Bb,
             const float* __restrict__ Cb,    const float* __restrict__ Qm,
             const float* __restrict__ Wx,    const float* __restrict__ Wh,
             const float* __restrict__ bx,    const float* __restrict__ bh,
             const float* __restrict__ Wo,    const float* __restrict__ bo,
             float* __restrict__ out)
{
    extern __shared__ float smem_f[];
    SAll& sh = *reinterpret_cast<SAll*>(smem_f);

    const int tid   = threadIdx.x;
    const int lane  = tid & 31;
    const int wid   = tid >> 5;
    const int chain = wid >> 1;
    const int cw    = wid & 1;          // 0 = spine (chol), 1 = helper
    const int barid = chain + 1;
    SC& C = sh.c[chain];
    const unsigned b = (unsigned)blockIdx.x * 2u + (unsigned)chain;

#define CBAR() asm volatile("bar.sync %0, 64;" :: "r"(barid) : "memory")

    // ---- one-time weight tables ---------------------------------------------
    for (int i = tid; i < 1024; i += 128) {
        int k = i >> 5, row = i & 31, e = row * 32 + k;
        sh.w.AmT[i] = make_float4(Ab[e], Ab[1024 + e], Ab[2048 + e], Ab[3072 + e]);
        sh.w.QT[i]  = Qm[e];
    }
    for (int i = tid; i < 512; i += 128)
        sh.w.CmS[i] = make_float4(Cb[i], Cb[512 + i], Cb[1024 + i], Cb[1536 + i]);
    for (int i = tid; i < 256; i += 128) {
        sh.w.BmS[i] = make_float4(Bb[i], Bb[256 + i], Bb[512 + i], Bb[768 + i]);
        int j = i >> 5, row = i & 31, e = row * 8 + j;
        sh.w.BmT[i] = make_float4(Bb[e], Bb[256 + e], Bb[512 + e], Bb[768 + e]);
    }
    for (int i = tid; i < 2048; i += 128) {
        int hh = i >> 5, l = i & 31, e = hh * 192 + l;
        sh.w.Wh4[i] = make_float4(Wh[e], Wh[e + 32], Wh[e + 64], Wh[e + 96]);
        sh.w.Wh2[i] = make_float2(Wh[e + 128], Wh[e + 160]);
    }
    for (int i = tid; i < 1024; i += 128) {
        int k = i >> 5, l = i & 31, e = k * 192 + l;
        sh.w.Wx4[i] = make_float4(Wx[e], Wx[e + 32], Wx[e + 64], Wx[e + 96]);
        sh.w.Wx2[i] = make_float2(Wx[e + 128], Wx[e + 160]);
    }
    if (tid < 64) sh.w.Wo4[tid] = make_float4(Wo[tid*4], Wo[tid*4+1], Wo[tid*4+2], Wo[tid*4+3]);
    for (int i = tid; i < 192; i += 128) { sh.w.bhs[i] = bh[i]; sh.w.bxs[i] = bx[i]; }

    // ---- per-chain state -----------------------------------------------------
    float al0 = alpha0[b*4u+0], al1 = alpha0[b*4u+1];
    float al2 = alpha0[b*4u+2], al3 = alpha0[b*4u+3];
    float ep_cur = 0.f;                 // spine
    float mu_own = 0.f, u_cur = 0.f;    // helper
    float hown0 = 0.f, hown1 = 0.f, bo0 = 0.f, bo1 = 0.f, bo2 = 0.f, bo3 = 0.f;

    if (cw == 0) {
        ep_cur = eps_g[(b * TLEN) * 32u + lane];
    } else {
        mu_own = mu0[b * 32u + lane];
        u_cur  = (lane < 8) ? u_f[(b * TLEN) * 8u + lane] : 0.f;
        hown0 = h0[b*64u + lane]; hown1 = h0[b*64u + 32 + lane];
        bo0 = bo[0]; bo1 = bo[1]; bo2 = bo[2]; bo3 = bo[3];
    }
    __syncthreads();
    if (cw == 0) {
        float a[32];
#pragma unroll
        for (int i = 0; i < 8; ++i) {
            float4 v = *(const float4*)(Sig0 + b * 1024u + (unsigned)(lane * 32 + 4 * i));
            a[4*i] = v.x; a[4*i+1] = v.y; a[4*i+2] = v.z; a[4*i+3] = v.w;
        }
        chol_init(a, lane, C.Ls);
    }
    __syncthreads();

#pragma unroll 1
    for (int t = 0; t < TLEN; ++t) {
        const unsigned bt  = b * TLEN + (unsigned)t;
        const unsigned btn = bt + (t < TLEN - 1 ? 1u : 0u);

        // ===== P0: spine A-mixture -> As4; helper C/B mixtures + outs =========
        if (cw == 0) {
#pragma unroll
            for (int k = 0; k < 32; k += 4) {
                float4 r0 = make_float4(
                    mix4(sh.w.AmT[(k+0) * 32 + lane], al0, al1, al2, al3),
                    mix4(sh.w.AmT[(k+1) * 32 + lane], al0, al1, al2, al3),
                    mix4(sh.w.AmT[(k+2) * 32 + lane], al0, al1, al2, al3),
                    mix4(sh.w.AmT[(k+3) * 32 + lane], al0, al1, al2, al3));
                *(float4*)&C.As4[lane * 36 + k] = r0;
            }
        } else {
#pragma unroll
            for (int e = 0; e < 16; ++e) {
                float cv = mix4(sh.w.CmS[e * 32 + lane], al0, al1, al2, al3);
                C.Cts[lane * 17 + e] = cv;
                out[OFF_CT + bt * 512u + (unsigned)(e * 32 + lane)] = cv;
            }
#pragma unroll
            for (int e = 0; e < 8; ++e)
                out[OFF_BT + bt * 256u + (unsigned)(e * 32 + lane)] =
                    mix4(sh.w.BmS[e * 32 + lane], al0, al1, al2, al3);
        }
        CBAR();

        // ===== P1: spine G-high + S-high; helper A_t out + mu + G-low + S-low =
        float sregH[32];
        if (cw == 0) {
            float ar[32];
#pragma unroll
            for (int i = 0; i < 8; ++i) {
                float4 v = *(const float4*)&C.As4[lane * 36 + 4 * i];
                ar[4*i] = v.x; ar[4*i+1] = v.y; ar[4*i+2] = v.z; ar[4*i+3] = v.w;
            }
            float g[16];
#pragma unroll
            for (int i = 0; i < 16; ++i) g[i] = 0.f;
#pragma unroll
            for (int jb = 0; jb < 4; ++jb) {
#pragma unroll
                for (int k = 16 + 4 * jb; k < 32; ++k) {
                    float ak = ar[k];
                    float4 lv = *(const float4*)&C.Ls[k * 36 + 16 + 4 * jb];
                    g[4*jb+0] = fmaf(ak, lv.x, g[4*jb+0]);
                    g[4*jb+1] = fmaf(ak, lv.y, g[4*jb+1]);
                    g[4*jb+2] = fmaf(ak, lv.z, g[4*jb+2]);
                    g[4*jb+3] = fmaf(ak, lv.w, g[4*jb+3]);
                }
            }
#pragma unroll
            for (int i = 0; i < 4; ++i)
                *(float4*)&C.Gs[lane * 36 + 16 + 4 * i] =
                    make_float4(g[4*i], g[4*i+1], g[4*i+2], g[4*i+3]);
            __syncwarp();
#pragma unroll
            for (int j = 0; j < 32; ++j) {     // S-high partial + Q fold
                const float4* Gr = (const float4*)&C.Gs[j * 36 + 16];
                float a0 = sh.w.QT[j * 32 + lane], a1 = 0.f, a2 = 0.f, a3 = 0.f;
#pragma unroll
                for (int i = 0; i < 4; ++i) {
                    float4 gv = Gr[i];
                    a0 = fmaf(g[4*i+0], gv.x, a0);
                    a1 = fmaf(g[4*i+1], gv.y, a1);
                    a2 = fmaf(g[4*i+2], gv.z, a2);
                    a3 = fmaf(g[4*i+3], gv.w, a3);
                }
                sregH[j] = (a0 + a1) + (a2 + a3);
            }
        } else {
            float ar2[32];
#pragma unroll
            for (int i = 0; i < 8; ++i) {
                float4 v = *(const float4*)&C.As4[lane * 36 + 4 * i];
                ar2[4*i] = v.x; ar2[4*i+1] = v.y; ar2[4*i+2] = v.z; ar2[4*i+3] = v.w;
                *(float4*)(out + OFF_AT + bt * 1024u + (unsigned)(lane * 32 + 4 * i)) = v;
            }
            // mu_next = A_t mu + B_t u (helper owns mu/u now)
            {
                float m0 = 0.f, m1 = 0.f;
#pragma unroll
                for (int k = 0; k < 32; k += 2) {
                    m0 = fmaf(ar2[k],     __shfl_sync(FULLMASK, mu_own, k),     m0);
                    m1 = fmaf(ar2[k + 1], __shfl_sync(FULLMASK, mu_own, k + 1), m1);
                }
#pragma unroll
                for (int j = 0; j < 8; ++j) {
                    float bj = mix4(sh.w.BmT[j * 32 + lane], al0, al1, al2, al3);
                    m0 = fmaf(bj, __shfl_sync(FULLMASK, u_cur, j), m0);
                }
                float mu_new = m0 + m1;
                out[OFF_MU + bt * 32u + lane] = mu_new;
                C.mus[lane] = mu_new;
                mu_own = mu_new;
                u_cur = (lane < 8) ? u_f[btn * 8u + lane] : 0.f;
            }
            // G cols 0..15 (k >= 4jb)
            float g[16];
#pragma unroll
            for (int i = 0; i < 16; ++i) g[i] = 0.f;
#pragma unroll
            for (int jb = 0; jb < 4; ++jb) {
#pragma unroll
                for (int k = 4 * jb; k < 32; ++k) {
                    float ak = ar2[k];
                    float4 lv = *(const float4*)&C.Ls[k * 36 + 4 * jb];
                    g[4*jb+0] = fmaf(ak, lv.x, g[4*jb+0]);
                    g[4*jb+1] = fmaf(ak, lv.y, g[4*jb+1]);
                    g[4*jb+2] = fmaf(ak, lv.z, g[4*jb+2]);
                    g[4*jb+3] = fmaf(ak, lv.w, g[4*jb+3]);
                }
            }
#pragma unroll
            for (int i = 0; i < 4; ++i)
                *(float4*)&C.Gs[lane * 36 + 4 * i] =
                    make_float4(g[4*i], g[4*i+1], g[4*i+2], g[4*i+3]);
            __syncwarp();
#pragma unroll
            for (int j = 0; j < 32; ++j) {
                const float4* Gr = (const float4*)&C.Gs[j * 36];
                float a0 = 0.f, a1 = 0.f, a2 = 0.f, a3 = 0.f;
#pragma unroll
                for (int i = 0; i < 4; ++i) {
                    float4 gv = Gr[i];
                    a0 = fmaf(g[4*i+0], gv.x, a0);
                    a1 = fmaf(g[4*i+1], gv.y, a1);
                    a2 = fmaf(g[4*i+2], gv.z, a2);
                    a3 = fmaf(g[4*i+3], gv.w, a3);
                }
                sregH[j] = (a0 + a1) + (a2 + a3);
            }
#pragma unroll
            for (int i = 0; i < 8; ++i)
                *(float4*)&C.Ss1[lane * 36 + 4 * i] =
                    make_float4(sregH[4*i], sregH[4*i+1], sregH[4*i+2], sregH[4*i+3]);
        }
        CBAR();

        // ===== P2: spine assemble + Sigma out + FUSED chol(z,gx,a_t); helper gh
        float gha[6];
        if (cw == 0) {
            float mu_new = C.mus[lane];
#pragma unroll
            for (int i = 0; i < 8; ++i) {
                float4 v = *(const float4*)&C.Ss1[lane * 36 + 4 * i];
                sregH[4*i+0] += v.x; sregH[4*i+1] += v.y;
                sregH[4*i+2] += v.z; sregH[4*i+3] += v.w;
            }
#pragma unroll
            for (int i = 0; i < 8; ++i)
                *(float4*)(out + OFF_SIG + bt * 1024u + (unsigned)(lane * 32 + 4 * i)) =
                    make_float4(sregH[4*i], sregH[4*i+1], sregH[4*i+2], sregH[4*i+3]);

            // fused Cholesky: z, gx, a_t in the d-chain shadows
            float zacc = mu_new;
            float gxa0 = sh.w.bxs[lane],       gxa1 = sh.w.bxs[lane + 32];
            float gxa2 = sh.w.bxs[lane + 64],  gxa3 = sh.w.bxs[lane + 96];
            float gxa4 = sh.w.bxs[lane + 128], gxa5 = sh.w.bxs[lane + 160];
            float at_acc = 0.f;
            const int lr = lane & 15;
#pragma unroll
            for (int j = 0; j < 32; ++j) {
                float d   = __shfl_sync(FULLMASK, sregH[j], j);
                float rs  = rsqrtf(d);
                float lij = sregH[j] * rs;
                sregH[j] = lij;
                float ej = __shfl_sync(FULLMASK, ep_cur, j);
                if (lane >= j) zacc = fmaf(lij, ej, zacc);
                float zj = __shfl_sync(FULLMASK, zacc, j);   // final z[j]
                {
                    float4 w4 = sh.w.Wx4[j * 32 + lane];
                    float2 w2 = sh.w.Wx2[j * 32 + lane];
                    gxa0 = fmaf(zj, w4.x, gxa0); gxa1 = fmaf(zj, w4.y, gxa1);
                    gxa2 = fmaf(zj, w4.z, gxa2); gxa3 = fmaf(zj, w4.w, gxa3);
                    gxa4 = fmaf(zj, w2.x, gxa4); gxa5 = fmaf(zj, w2.y, gxa5);
                    at_acc = fmaf(C.Cts[j * 17 + lr], zj, at_acc);
                }
                float lsq = lij * lij;
#pragma unroll
                for (int k = j + 1; k < 32; ++k) {
                    float lkj = __shfl_sync(FULLMASK, lij, k);
                    if (k == lane) sregH[k] -= lsq;
                    else           sregH[k] = fmaf(-lij, lkj, sregH[k]);
                }
            }
#pragma unroll
            for (int k = 0; k < 32; ++k) if (k > lane) sregH[k] = 0.f;
#pragma unroll
            for (int i = 0; i < 8; ++i)
                *(float4*)&C.Ls[lane * 36 + 4 * i] =
                    make_float4(sregH[4*i], sregH[4*i+1], sregH[4*i+2], sregH[4*i+3]);

            out[OFF_Z + bt * 32u + lane] = zacc;
            if (lane < 16) out[OFF_A + bt * 16u + lane] = at_acc;
            C.gxs[lane]       = gxa0; C.gxs[lane + 32]  = gxa1;
            C.gxs[lane + 64]  = gxa2; C.gxs[lane + 96]  = gxa3;
            C.gxs[lane + 128] = gxa4; C.gxs[lane + 160] = gxa5;
            ep_cur = eps_g[btn * 32u + lane];
        } else {
#pragma unroll
            for (int m = 0; m < 6; ++m) gha[m] = sh.w.bhs[lane + 32 * m];
#pragma unroll 4
            for (int hh = 0; hh < 32; ++hh) {
                float hv = __shfl_sync(FULLMASK, hown0, hh);
                float4 w4 = sh.w.Wh4[hh * 32 + lane];
                float2 w2 = sh.w.Wh2[hh * 32 + lane];
                gha[0] = fmaf(hv, w4.x, gha[0]); gha[1] = fmaf(hv, w4.y, gha[1]);
                gha[2] = fmaf(hv, w4.z, gha[2]); gha[3] = fmaf(hv, w4.w, gha[3]);
                gha[4] = fmaf(hv, w2.x, gha[4]); gha[5] = fmaf(hv, w2.y, gha[5]);
            }
#pragma unroll 4
            for (int hh = 0; hh < 32; ++hh) {
                float hv = __shfl_sync(FULLMASK, hown1, hh);
                float4 w4 = sh.w.Wh4[(hh + 32) * 32 + lane];
                float2 w2 = sh.w.Wh2[(hh + 32) * 32 + lane];
                gha[0] = fmaf(hv, w4.x, gha[0]); gha[1] = fmaf(hv, w4.y, gha[1]);
                gha[2] = fmaf(hv, w4.z, gha[2]); gha[3] = fmaf(hv, w4.w, gha[3]);
                gha[4] = fmaf(hv, w2.x, gha[4]); gha[5] = fmaf(hv, w2.y, gha[5]);
            }
        }
        CBAR();

        // ===== P3: helper GRU + softmax ========================================
        if (cw == 1) {
            float gx0 = C.gxs[lane],       gx1 = C.gxs[lane + 32];
            float gx2 = C.gxs[lane + 64],  gx3 = C.gxs[lane + 96];
            float gx4 = C.gxs[lane + 128], gx5 = C.gxs[lane + 160];
            float r0 = fast_sigmoid(gx0 + gha[0]);
            float r1 = fast_sigmoid(gx1 + gha[1]);
            float zg0 = fast_sigmoid(gx2 + gha[2]);
            float zg1 = fast_sigmoid(gx3 + gha[3]);
            float n0 = fast_tanh(gx4 + r0 * gha[4]);
            float n1 = fast_tanh(gx5 + r1 * gha[5]);
            hown0 = (1.f - zg0) * n0 + zg0 * hown0;
            hown1 = (1.f - zg1) * n1 + zg1 * hown1;
            float4 w0 = sh.w.Wo4[lane], w1 = sh.w.Wo4[lane + 32];
            float p0 = fmaf(hown0, w0.x, hown1 * w1.x);
            float p1 = fmaf(hown0, w0.y, hown1 * w1.y);
            float p2 = fmaf(hown0, w0.z, hown1 * w1.z);
            float p3 = fmaf(hown0, w0.w, hown1 * w1.w);
#pragma unroll
            for (int off = 16; off; off >>= 1) {
                p0 += __shfl_xor_sync(FULLMASK, p0, off);
                p1 += __shfl_xor_sync(FULLMASK, p1, off);
                p2 += __shfl_xor_sync(FULLMASK, p2, off);
                p3 += __shfl_xor_sync(FULLMASK, p3, off);
            }
            float o0 = p0 + bo0, o1 = p1 + bo1, o2 = p2 + bo2, o3 = p3 + bo3;
            float mx = fmaxf(fmaxf(o0, o1), fmaxf(o2, o3));
            float e0 = __expf(o0 - mx), e1 = __expf(o1 - mx);
            float e2 = __expf(o2 - mx), e3 = __expf(o3 - mx);
            float inv = 1.f / (e0 + e1 + e2 + e3);
            if (lane == 0) {
                C.alsh[0] = e0 * inv; C.alsh[1] = e1 * inv;
                C.alsh[2] = e2 * inv; C.alsh[3] = e3 * inv;
            }
        }
        CBAR();
        al0 = C.alsh[0]; al1 = C.alsh[1]; al2 = C.alsh[2]; al3 = C.alsh[3];
    }
#undef CBAR
}

extern "C" void kernel_launch(void* const* d_in, const int* in_sizes, int n_in,
                              void* d_out, int out_size)
{
    size_t shbytes = sizeof(SAll);
    cudaFuncSetAttribute(lgssm_kernel,
                         cudaFuncAttributeMaxDynamicSharedMemorySize, (int)shbytes);
    lgssm_kernel<<<128, 128, shbytes>>>(
        (const float*)d_in[0],  (const float*)d_in[1],  (const float*)d_in[2],
        (const float*)d_in[3],  (const float*)d_in[4],  (const float*)d_in[5],
        (const float*)d_in[6],  (const float*)d_in[7],  (const float*)d_in[8],
        (const float*)d_in[9],  (const float*)d_in[10], (const float*)d_in[11],
        (const float*)d_in[12], (const float*)d_in[13], (const float*)d_in[14],
        (const float*)d_in[15], (float*)d_out);
}

// round 16
// speedup vs baseline: 1.0198x; 1.0198x over previous
#include <cuda_runtime.h>

#define TLEN 256
#define FULLMASK 0xffffffffu

#define OFF_Z   0u
#define OFF_MU  2097152u
#define OFF_SIG 4194304u
#define OFF_A   71303168u
#define OFF_AT  72351744u
#define OFF_BT  139460608u
#define OFF_CT  156237824u

struct SW {
    float4 AmT[1024];      // [k*32+row] = (A0..A3)[row][k]
    float4 CmS[512];       // [flat]
    float4 BmS[256];       // [flat]
    float4 BmT[256];       // [j*32+row]
    float  QT[1024];       // [k*32+row] = Q[row][k]
    float4 Wh4[2048];      // [hh*32+lane] = Wh[hh*192+lane + {0,32,64,96}]
    float2 Wh2[2048];      // [hh*32+lane] = Wh[hh*192+lane + {128,160}]
    float4 Wx4[1024];      // [k*32+lane]  = Wx[k*192+lane + {0,32,64,96}]
    float2 Wx2[1024];      // [k*32+lane]  = Wx[k*192+lane + {128,160}]
    float4 Wo4[64];
    float  bhs[192], bxs[192];
};
struct SC {
    float Ls[32 * 36];     // L rows (float4 pad)
    float Gs[32 * 36];     // G rows (hi half: spine, lo half: helper)
    float Ss1[32 * 36];    // helper's S partial (k<16)
    float Cts[32 * 17];    // [c*17+r] = C_t[r][c]
    float gxs[192];        // spine -> helper gate inputs
    float alsh[4];
};
struct SAll { SW w; SC c[2]; };

__device__ __forceinline__ float fast_tanh(float x) {
    float y; asm("tanh.approx.f32 %0, %1;" : "=f"(y) : "f"(x)); return y;
}
__device__ __forceinline__ float fast_sigmoid(float x) {
    return 0.5f + 0.5f * fast_tanh(0.5f * x);
}
__device__ __forceinline__ float mix4(float4 v, float a0, float a1, float a2, float a3) {
    return fmaf(v.x, a0, fmaf(v.y, a1, fmaf(v.z, a2, v.w * a3)));
}

__device__ __forceinline__ void chol_init(float a[32], int lane, float* Ls)
{
#pragma unroll
    for (int j = 0; j < 32; ++j) {
        float d   = __shfl_sync(FULLMASK, a[j], j);
        float rs  = rsqrtf(d);
        float lij = a[j] * rs;
        a[j] = lij;
        float lsq = lij * lij;
#pragma unroll
        for (int k = j + 1; k < 32; ++k) {
            float lkj = __shfl_sync(FULLMASK, lij, k);
            if (k == lane) a[k] -= lsq;
            else           a[k] = fmaf(-lij, lkj, a[k]);
        }
    }
#pragma unroll
    for (int k = 0; k < 32; ++k) if (k > lane) a[k] = 0.f;
#pragma unroll
    for (int i = 0; i < 8; ++i)
        *(float4*)&Ls[lane * 36 + 4 * i] =
            make_float4(a[4*i], a[4*i+1], a[4*i+2], a[4*i+3]);
}

__global__ void __launch_bounds__(128, 1)
lgssm_kernel(const float* __restrict__ mu0,   const float* __restrict__ Sig0,
             const float* __restrict__ alpha0,const float* __restrict__ h0,
             const float* __restrict__ u_f,   const float* __restrict__ eps_g,
             const float* __restrict__ Ab,    const float* __restrict__ Bb,
             const float* __restrict__ Cb,    const float* __restrict__ Qm,
             const float* __restrict__ Wx,    const float* __restrict__ Wh,
             const float* __restrict__ bx,    const float* __restrict__ bh,
             const float* __restrict__ Wo,    const float* __restrict__ bo,
             float* __restrict__ out)
{
    extern __shared__ float smem_f[];
    SAll& sh = *reinterpret_cast<SAll*>(smem_f);

    const int tid   = threadIdx.x;
    const int lane  = tid & 31;
    const int wid   = tid >> 5;
    const int chain = wid >> 1;
    const int cw    = wid & 1;          // 0 = spine (chol), 1 = helper
    const int barid = chain + 1;
    SC& C = sh.c[chain];
    const unsigned b = (unsigned)blockIdx.x * 2u + (unsigned)chain;

#define CBAR() asm volatile("bar.sync %0, 64;" :: "r"(barid) : "memory")

    // ---- one-time weight tables ---------------------------------------------
    for (int i = tid; i < 1024; i += 128) {
        int k = i >> 5, row = i & 31, e = row * 32 + k;
        sh.w.AmT[i] = make_float4(Ab[e], Ab[1024 + e], Ab[2048 + e], Ab[3072 + e]);
        sh.w.QT[i]  = Qm[e];
    }
    for (int i = tid; i < 512; i += 128)
        sh.w.CmS[i] = make_float4(Cb[i], Cb[512 + i], Cb[1024 + i], Cb[1536 + i]);
    for (int i = tid; i < 256; i += 128) {
        sh.w.BmS[i] = make_float4(Bb[i], Bb[256 + i], Bb[512 + i], Bb[768 + i]);
        int j = i >> 5, row = i & 31, e = row * 8 + j;
        sh.w.BmT[i] = make_float4(Bb[e], Bb[256 + e], Bb[512 + e], Bb[768 + e]);
    }
    for (int i = tid; i < 2048; i += 128) {
        int hh = i >> 5, l = i & 31, e = hh * 192 + l;
        sh.w.Wh4[i] = make_float4(Wh[e], Wh[e + 32], Wh[e + 64], Wh[e + 96]);
        sh.w.Wh2[i] = make_float2(Wh[e + 128], Wh[e + 160]);
    }
    for (int i = tid; i < 1024; i += 128) {
        int k = i >> 5, l = i & 31, e = k * 192 + l;
        sh.w.Wx4[i] = make_float4(Wx[e], Wx[e + 32], Wx[e + 64], Wx[e + 96]);
        sh.w.Wx2[i] = make_float2(Wx[e + 128], Wx[e + 160]);
    }
    if (tid < 64) sh.w.Wo4[tid] = make_float4(Wo[tid*4], Wo[tid*4+1], Wo[tid*4+2], Wo[tid*4+3]);
    for (int i = tid; i < 192; i += 128) { sh.w.bhs[i] = bh[i]; sh.w.bxs[i] = bx[i]; }

    // ---- per-chain state -----------------------------------------------------
    float al0 = alpha0[b*4u+0], al1 = alpha0[b*4u+1];
    float al2 = alpha0[b*4u+2], al3 = alpha0[b*4u+3];
    float mu_own = 0.f, ep_cur = 0.f, u_cur = 0.f;           // spine
    float hown0 = 0.f, hown1 = 0.f, bo0 = 0.f, bo1 = 0.f, bo2 = 0.f, bo3 = 0.f;

    if (cw == 0) {
        mu_own = mu0[b * 32u + lane];
        ep_cur = eps_g[(b * TLEN) * 32u + lane];
        u_cur  = (lane < 8) ? u_f[(b * TLEN) * 8u + lane] : 0.f;
    } else {
        hown0 = h0[b*64u + lane]; hown1 = h0[b*64u + 32 + lane];
        bo0 = bo[0]; bo1 = bo[1]; bo2 = bo[2]; bo3 = bo[3];
    }
    __syncthreads();
    if (cw == 0) {
        float a[32];
#pragma unroll
        for (int i = 0; i < 8; ++i) {
            float4 v = *(const float4*)(Sig0 + b * 1024u + (unsigned)(lane * 32 + 4 * i));
            a[4*i] = v.x; a[4*i+1] = v.y; a[4*i+2] = v.z; a[4*i+3] = v.w;
        }
        chol_init(a, lane, C.Ls);
    }
    __syncthreads();

#pragma unroll 1
    for (int t = 0; t < TLEN; ++t) {
        const unsigned bt  = b * TLEN + (unsigned)t;
        const unsigned btn = bt + (t < TLEN - 1 ? 1u : 0u);
        float sregH[32], gha[6];
        float mu_new = 0.f, ep_nxt = 0.f, u_nxt = 0.f;

        // ===== P01 (merged): each warp computes its own A-mixture ==============
        if (cw == 0) {
            ep_nxt = eps_g[btn * 32u + lane];
            u_nxt  = (lane < 8) ? u_f[btn * 8u + lane] : 0.f;
            float ar[32];
#pragma unroll
            for (int k = 0; k < 32; ++k)
                ar[k] = mix4(sh.w.AmT[k * 32 + lane], al0, al1, al2, al3);
            // mu_next = A_t mu + B_t u
            float m0 = 0.f, m1 = 0.f;
#pragma unroll
            for (int k = 0; k < 32; k += 2) {
                m0 = fmaf(ar[k],     __shfl_sync(FULLMASK, mu_own, k),     m0);
                m1 = fmaf(ar[k + 1], __shfl_sync(FULLMASK, mu_own, k + 1), m1);
            }
#pragma unroll
            for (int j = 0; j < 8; ++j) {
                float bj = mix4(sh.w.BmT[j * 32 + lane], al0, al1, al2, al3);
                m0 = fmaf(bj, __shfl_sync(FULLMASK, u_cur, j), m0);
            }
            mu_new = m0 + m1;
            out[OFF_MU + bt * 32u + lane] = mu_new;
#pragma unroll
            for (int i = 0; i < 8; ++i)     // A_t out from regs
                *(float4*)(out + OFF_AT + bt * 1024u + (unsigned)(lane * 32 + 4 * i)) =
                    make_float4(ar[4*i], ar[4*i+1], ar[4*i+2], ar[4*i+3]);
            // G cols 16..31 (L triangular: k >= 16+4jb)
            float g[16];
#pragma unroll
            for (int i = 0; i < 16; ++i) g[i] = 0.f;
#pragma unroll
            for (int jb = 0; jb < 4; ++jb) {
#pragma unroll
                for (int k = 16 + 4 * jb; k < 32; ++k) {
                    float ak = ar[k];
                    float4 lv = *(const float4*)&C.Ls[k * 36 + 16 + 4 * jb];
                    g[4*jb+0] = fmaf(ak, lv.x, g[4*jb+0]);
                    g[4*jb+1] = fmaf(ak, lv.y, g[4*jb+1]);
                    g[4*jb+2] = fmaf(ak, lv.z, g[4*jb+2]);
                    g[4*jb+3] = fmaf(ak, lv.w, g[4*jb+3]);
                }
            }
#pragma unroll
            for (int i = 0; i < 4; ++i)
                *(float4*)&C.Gs[lane * 36 + 16 + 4 * i] =
                    make_float4(g[4*i], g[4*i+1], g[4*i+2], g[4*i+3]);
            __syncwarp();
#pragma unroll
            for (int j = 0; j < 32; ++j) {  // S-high partial + Q fold
                const float4* Gr = (const float4*)&C.Gs[j * 36 + 16];
                float a0 = sh.w.QT[j * 32 + lane], a1 = 0.f, a2 = 0.f, a3 = 0.f;
#pragma unroll
                for (int i = 0; i < 4; ++i) {
                    float4 gv = Gr[i];
                    a0 = fmaf(g[4*i+0], gv.x, a0);
                    a1 = fmaf(g[4*i+1], gv.y, a1);
                    a2 = fmaf(g[4*i+2], gv.z, a2);
                    a3 = fmaf(g[4*i+3], gv.w, a3);
                }
                sregH[j] = (a0 + a1) + (a2 + a3);
            }
        } else {
#pragma unroll
            for (int e = 0; e < 16; ++e) {  // C mixture + out
                float cv = mix4(sh.w.CmS[e * 32 + lane], al0, al1, al2, al3);
                C.Cts[lane * 17 + e] = cv;
                out[OFF_CT + bt * 512u + (unsigned)(e * 32 + lane)] = cv;
            }
#pragma unroll
            for (int e = 0; e < 8; ++e)     // B mixture out
                out[OFF_BT + bt * 256u + (unsigned)(e * 32 + lane)] =
                    mix4(sh.w.BmS[e * 32 + lane], al0, al1, al2, al3);
            // redundant own A-mixture (kills the As4 hand-off + a barrier)
            float ar2[32];
#pragma unroll
            for (int k = 0; k < 32; ++k)
                ar2[k] = mix4(sh.w.AmT[k * 32 + lane], al0, al1, al2, al3);
            // G cols 0..15 (k >= 4jb)
            float g[16];
#pragma unroll
            for (int i = 0; i < 16; ++i) g[i] = 0.f;
#pragma unroll
            for (int jb = 0; jb < 4; ++jb) {
#pragma unroll
                for (int k = 4 * jb; k < 32; ++k) {
                    float ak = ar2[k];
                    float4 lv = *(const float4*)&C.Ls[k * 36 + 4 * jb];
                    g[4*jb+0] = fmaf(ak, lv.x, g[4*jb+0]);
                    g[4*jb+1] = fmaf(ak, lv.y, g[4*jb+1]);
                    g[4*jb+2] = fmaf(ak, lv.z, g[4*jb+2]);
                    g[4*jb+3] = fmaf(ak, lv.w, g[4*jb+3]);
                }
            }
#pragma unroll
            for (int i = 0; i < 4; ++i)
                *(float4*)&C.Gs[lane * 36 + 4 * i] =
                    make_float4(g[4*i], g[4*i+1], g[4*i+2], g[4*i+3]);
            __syncwarp();
            float sregL[32];
#pragma unroll
            for (int j = 0; j < 32; ++j) {  // S-low partial
                const float4* Gr = (const float4*)&C.Gs[j * 36];
                float a0 = 0.f, a1 = 0.f, a2 = 0.f, a3 = 0.f;
#pragma unroll
                for (int i = 0; i < 4; ++i) {
                    float4 gv = Gr[i];
                    a0 = fmaf(g[4*i+0], gv.x, a0);
                    a1 = fmaf(g[4*i+1], gv.y, a1);
                    a2 = fmaf(g[4*i+2], gv.z, a2);
                    a3 = fmaf(g[4*i+3], gv.w, a3);
                }
                sregL[j] = (a0 + a1) + (a2 + a3);
            }
#pragma unroll
            for (int i = 0; i < 8; ++i)
                *(float4*)&C.Ss1[lane * 36 + 4 * i] =
                    make_float4(sregL[4*i], sregL[4*i+1], sregL[4*i+2], sregL[4*i+3]);
        }
        CBAR();

        // ===== P2: spine assemble + Sigma out + FUSED chol(z,gx,a_t); helper gh
        if (cw == 0) {
#pragma unroll
            for (int i = 0; i < 8; ++i) {
                float4 v = *(const float4*)&C.Ss1[lane * 36 + 4 * i];
                sregH[4*i+0] += v.x; sregH[4*i+1] += v.y;
                sregH[4*i+2] += v.z; sregH[4*i+3] += v.w;
            }
#pragma unroll
            for (int i = 0; i < 8; ++i)
                *(float4*)(out + OFF_SIG + bt * 1024u + (unsigned)(lane * 32 + 4 * i)) =
                    make_float4(sregH[4*i], sregH[4*i+1], sregH[4*i+2], sregH[4*i+3]);

            // fused Cholesky: z, gx, a_t in the d-chain shadows
            float zacc = mu_new;
            float gxa0 = sh.w.bxs[lane],       gxa1 = sh.w.bxs[lane + 32];
            float gxa2 = sh.w.bxs[lane + 64],  gxa3 = sh.w.bxs[lane + 96];
            float gxa4 = sh.w.bxs[lane + 128], gxa5 = sh.w.bxs[lane + 160];
            float at_acc = 0.f;
            const int lr = lane & 15;
#pragma unroll
            for (int j = 0; j < 32; ++j) {
                float d   = __shfl_sync(FULLMASK, sregH[j], j);
                float rs  = rsqrtf(d);
                float lij = sregH[j] * rs;
                sregH[j] = lij;
                float ej = __shfl_sync(FULLMASK, ep_cur, j);
                if (lane >= j) zacc = fmaf(lij, ej, zacc);
                float zj = __shfl_sync(FULLMASK, zacc, j);   // final z[j]
                {
                    float4 w4 = sh.w.Wx4[j * 32 + lane];
                    float2 w2 = sh.w.Wx2[j * 32 + lane];
                    gxa0 = fmaf(zj, w4.x, gxa0); gxa1 = fmaf(zj, w4.y, gxa1);
                    gxa2 = fmaf(zj, w4.z, gxa2); gxa3 = fmaf(zj, w4.w, gxa3);
                    gxa4 = fmaf(zj, w2.x, gxa4); gxa5 = fmaf(zj, w2.y, gxa5);
                    at_acc = fmaf(C.Cts[j * 17 + lr], zj, at_acc);
                }
                float lsq = lij * lij;
#pragma unroll
                for (int k = j + 1; k < 32; ++k) {
                    float lkj = __shfl_sync(FULLMASK, lij, k);
                    if (k == lane) sregH[k] -= lsq;
                    else           sregH[k] = fmaf(-lij, lkj, sregH[k]);
                }
            }
#pragma unroll
            for (int k = 0; k < 32; ++k) if (k > lane) sregH[k] = 0.f;
#pragma unroll
            for (int i = 0; i < 8; ++i)
                *(float4*)&C.Ls[lane * 36 + 4 * i] =
                    make_float4(sregH[4*i], sregH[4*i+1], sregH[4*i+2], sregH[4*i+3]);

            out[OFF_Z + bt * 32u + lane] = zacc;
            if (lane < 16) out[OFF_A + bt * 16u + lane] = at_acc;
            C.gxs[lane]       = gxa0; C.gxs[lane + 32]  = gxa1;
            C.gxs[lane + 64]  = gxa2; C.gxs[lane + 96]  = gxa3;
            C.gxs[lane + 128] = gxa4; C.gxs[lane + 160] = gxa5;
            mu_own = mu_new; ep_cur = ep_nxt; u_cur = u_nxt;
        } else {
#pragma unroll
            for (int m = 0; m < 6; ++m) gha[m] = sh.w.bhs[lane + 32 * m];
#pragma unroll 4
            for (int hh = 0; hh < 32; ++hh) {
                float hv = __shfl_sync(FULLMASK, hown0, hh);
                float4 w4 = sh.w.Wh4[hh * 32 + lane];
                float2 w2 = sh.w.Wh2[hh * 32 + lane];
                gha[0] = fmaf(hv, w4.x, gha[0]); gha[1] = fmaf(hv, w4.y, gha[1]);
                gha[2] = fmaf(hv, w4.z, gha[2]); gha[3] = fmaf(hv, w4.w, gha[3]);
                gha[4] = fmaf(hv, w2.x, gha[4]); gha[5] = fmaf(hv, w2.y, gha[5]);
            }
#pragma unroll 4
            for (int hh = 0; hh < 32; ++hh) {
                float hv = __shfl_sync(FULLMASK, hown1, hh);
                float4 w4 = sh.w.Wh4[(hh + 32) * 32 + lane];
                float2 w2 = sh.w.Wh2[(hh + 32) * 32 + lane];
                gha[0] = fmaf(hv, w4.x, gha[0]); gha[1] = fmaf(hv, w4.y, gha[1]);
                gha[2] = fmaf(hv, w4.z, gha[2]); gha[3] = fmaf(hv, w4.w, gha[3]);
                gha[4] = fmaf(hv, w2.x, gha[4]); gha[5] = fmaf(hv, w2.y, gha[5]);
            }
        }
        CBAR();

        // ===== P3: helper GRU + softmax ========================================
        if (cw == 1) {
            float gx0 = C.gxs[lane],       gx1 = C.gxs[lane + 32];
            float gx2 = C.gxs[lane + 64],  gx3 = C.gxs[lane + 96];
            float gx4 = C.gxs[lane + 128], gx5 = C.gxs[lane + 160];
            float r0 = fast_sigmoid(gx0 + gha[0]);
            float r1 = fast_sigmoid(gx1 + gha[1]);
            float zg0 = fast_sigmoid(gx2 + gha[2]);
            float zg1 = fast_sigmoid(gx3 + gha[3]);
            float n0 = fast_tanh(gx4 + r0 * gha[4]);
            float n1 = fast_tanh(gx5 + r1 * gha[5]);
            hown0 = (1.f - zg0) * n0 + zg0 * hown0;
            hown1 = (1.f - zg1) * n1 + zg1 * hown1;
            float4 w0 = sh.w.Wo4[lane], w1 = sh.w.Wo4[lane + 32];
            float p0 = fmaf(hown0, w0.x, hown1 * w1.x);
            float p1 = fmaf(hown0, w0.y, hown1 * w1.y);
            float p2 = fmaf(hown0, w0.z, hown1 * w1.z);
            float p3 = fmaf(hown0, w0.w, hown1 * w1.w);
#pragma unroll
            for (int off = 16; off; off >>= 1) {
                p0 += __shfl_xor_sync(FULLMASK, p0, off);
                p1 += __shfl_xor_sync(FULLMASK, p1, off);
                p2 += __shfl_xor_sync(FULLMASK, p2, off);
                p3 += __shfl_xor_sync(FULLMASK, p3, off);
            }
            float o0 = p0 + bo0, o1 = p1 + bo1, o2 = p2 + bo2, o3 = p3 + bo3;
            float mx = fmaxf(fmaxf(o0, o1), fmaxf(o2, o3));
            float e0 = __expf(o0 - mx), e1 = __expf(o1 - mx);
            float e2 = __expf(o2 - mx), e3 = __expf(o3 - mx);
            float inv = 1.f / (e0 + e1 + e2 + e3);
            if (lane == 0) {
                C.alsh[0] = e0 * inv; C.alsh[1] = e1 * inv;
                C.alsh[2] = e2 * inv; C.alsh[3] = e3 * inv;
            }
        }
        CBAR();
        al0 = C.alsh[0]; al1 = C.alsh[1]; al2 = C.alsh[2]; al3 = C.alsh[3];
    }
#undef CBAR
}

extern "C" void kernel_launch(void* const* d_in, const int* in_sizes, int n_in,
                              void* d_out, int out_size)
{
    size_t shbytes = sizeof(SAll);
    cudaFuncSetAttribute(lgssm_kernel,
                         cudaFuncAttributeMaxDynamicSharedMemorySize, (int)shbytes);
    lgssm_kernel<<<128, 128, shbytes>>>(
        (const float*)d_in[0],  (const float*)d_in[1],  (const float*)d_in[2],
        (const float*)d_in[3],  (const float*)d_in[4],  (const float*)d_in[5],
        (const float*)d_in[6],  (const float*)d_in[7],  (const float*)d_in[8],
        (const float*)d_in[9],  (const float*)d_in[10], (const float*)d_in[11],
        (const float*)d_in[12], (const float*)d_in[13], (const float*)d_in[14],
        (const float*)d_in[15], (float*)d_out);
}

// round 17
// speedup vs baseline: 1.0383x; 1.0182x over previous
#include <cuda_runtime.h>

#define TLEN 256
#define FULLMASK 0xffffffffu

#define OFF_Z   0u
#define OFF_MU  2097152u
#define OFF_SIG 4194304u
#define OFF_A   71303168u
#define OFF_AT  72351744u
#define OFF_BT  139460608u
#define OFF_CT  156237824u

typedef unsigned long long u64;

struct SW {
    float4 AmT[1024];      // [k*32+row] = (A0..A3)[row][k]
    float4 CmS[512];       // [flat]
    float4 BmS[256];       // [flat]
    float4 BmT[256];       // [j*32+row]
    float  QT[1024];       // [k*32+row] = Q[row][k]
    float4 Wh4[2048];      // [hh*32+lane] = Wh[hh*192+lane + {0,32,64,96}]
    float2 Wh2[2048];      // [hh*32+lane] = Wh[hh*192+lane + {128,160}]
    float4 Wx4[1024];      // [k*32+lane]  = Wx[k*192+lane + {0,32,64,96}]
    float2 Wx2[1024];      // [k*32+lane]  = Wx[k*192+lane + {128,160}]
    float4 Wo4[64];
    float  bhs[192], bxs[192];
};
struct SC {
    float Ls[32 * 36];     // L rows (float4 pad)
    float Gs[32 * 36];     // G rows (hi: spine, lo: helper)
    float Ss1[32 * 36];    // helper's S partial (k<16)
    float SsF[32 * 36];    // assembled S rows (spine -> helper Sigma store)
    float Cts[32 * 17];    // [c*17+r] = C_t[r][c]
    float gxs[192];        // spine -> helper gate inputs
    float alsh[4];
};
struct SAll { SW w; SC c[2]; };

__device__ __forceinline__ float fast_tanh(float x) {
    float y; asm("tanh.approx.f32 %0, %1;" : "=f"(y) : "f"(x)); return y;
}
__device__ __forceinline__ float fast_sigmoid(float x) {
    return 0.5f + 0.5f * fast_tanh(0.5f * x);
}
__device__ __forceinline__ float mix4(float4 v, float a0, float a1, float a2, float a3) {
    return fmaf(v.x, a0, fmaf(v.y, a1, fmaf(v.z, a2, v.w * a3)));
}
__device__ __forceinline__ u64 pack2(float lo, float hi) {
    u64 r;
    asm("mov.b64 %0, {%1, %2};" : "=l"(r) : "r"(__float_as_uint(lo)), "r"(__float_as_uint(hi)));
    return r;
}
__device__ __forceinline__ void unpack2(u64 v, float& lo, float& hi) {
    unsigned a, b;
    asm("mov.b64 {%0, %1}, %2;" : "=r"(a), "=r"(b) : "l"(v));
    lo = __uint_as_float(a); hi = __uint_as_float(b);
}
__device__ __forceinline__ u64 ffma2(u64 a, u64 b, u64 c) {
    u64 d;
    asm("fma.rn.f32x2 %0, %1, %2, %3;" : "=l"(d) : "l"(a), "l"(b), "l"(c));
    return d;
}

__device__ __forceinline__ void chol_init(float a[32], int lane, float* Ls)
{
#pragma unroll
    for (int j = 0; j < 32; ++j) {
        float d   = __shfl_sync(FULLMASK, a[j], j);
        float rs  = rsqrtf(d);
        float lij = a[j] * rs;
        a[j] = lij;
        float lsq = lij * lij;
#pragma unroll
        for (int k = j + 1; k < 32; ++k) {
            float lkj = __shfl_sync(FULLMASK, lij, k);
            if (k == lane) a[k] -= lsq;
            else           a[k] = fmaf(-lij, lkj, a[k]);
        }
    }
#pragma unroll
    for (int k = 0; k < 32; ++k) if (k > lane) a[k] = 0.f;
#pragma unroll
    for (int i = 0; i < 8; ++i)
        *(float4*)&Ls[lane * 36 + 4 * i] =
            make_float4(a[4*i], a[4*i+1], a[4*i+2], a[4*i+3]);
}

__global__ void __launch_bounds__(128, 1)
lgssm_kernel(const float* __restrict__ mu0,   const float* __restrict__ Sig0,
             const float* __restrict__ alpha0,const float* __restrict__ h0,
             const float* __restrict__ u_f,   const float* __restrict__ eps_g,
             const float* __restrict__ Ab,    const float* __restrict__ Bb,
             const float* __restrict__ Cb,    const float* __restrict__ Qm,
             const float* __restrict__ Wx,    const float* __restrict__ Wh,
             const float* __restrict__ bx,    const float* __restrict__ bh,
             const float* __restrict__ Wo,    const float* __restrict__ bo,
             float* __restrict__ out)
{
    extern __shared__ float smem_f[];
    SAll& sh = *reinterpret_cast<SAll*>(smem_f);

    const int tid   = threadIdx.x;
    const int lane  = tid & 31;
    const int wid   = tid >> 5;
    const int chain = wid >> 1;
    const int cw    = wid & 1;          // 0 = spine (chol), 1 = helper
    const int barid = chain + 1;
    SC& C = sh.c[chain];
    const unsigned b = (unsigned)blockIdx.x * 2u + (unsigned)chain;

#define CBAR() asm volatile("bar.sync %0, 64;" :: "r"(barid) : "memory")

    // ---- one-time weight tables ---------------------------------------------
    for (int i = tid; i < 1024; i += 128) {
        int k = i >> 5, row = i & 31, e = row * 32 + k;
        sh.w.AmT[i] = make_float4(Ab[e], Ab[1024 + e], Ab[2048 + e], Ab[3072 + e]);
        sh.w.QT[i]  = Qm[e];
    }
    for (int i = tid; i < 512; i += 128)
        sh.w.CmS[i] = make_float4(Cb[i], Cb[512 + i], Cb[1024 + i], Cb[1536 + i]);
    for (int i = tid; i < 256; i += 128) {
        sh.w.BmS[i] = make_float4(Bb[i], Bb[256 + i], Bb[512 + i], Bb[768 + i]);
        int j = i >> 5, row = i & 31, e = row * 8 + j;
        sh.w.BmT[i] = make_float4(Bb[e], Bb[256 + e], Bb[512 + e], Bb[768 + e]);
    }
    for (int i = tid; i < 2048; i += 128) {
        int hh = i >> 5, l = i & 31, e = hh * 192 + l;
        sh.w.Wh4[i] = make_float4(Wh[e], Wh[e + 32], Wh[e + 64], Wh[e + 96]);
        sh.w.Wh2[i] = make_float2(Wh[e + 128], Wh[e + 160]);
    }
    for (int i = tid; i < 1024; i += 128) {
        int k = i >> 5, l = i & 31, e = k * 192 + l;
        sh.w.Wx4[i] = make_float4(Wx[e], Wx[e + 32], Wx[e + 64], Wx[e + 96]);
        sh.w.Wx2[i] = make_float2(Wx[e + 128], Wx[e + 160]);
    }
    if (tid < 64) sh.w.Wo4[tid] = make_float4(Wo[tid*4], Wo[tid*4+1], Wo[tid*4+2], Wo[tid*4+3]);
    for (int i = tid; i < 192; i += 128) { sh.w.bhs[i] = bh[i]; sh.w.bxs[i] = bx[i]; }

    // ---- per-chain state -----------------------------------------------------
    float al0 = alpha0[b*4u+0], al1 = alpha0[b*4u+1];
    float al2 = alpha0[b*4u+2], al3 = alpha0[b*4u+3];
    float mu_own = 0.f, ep_cur = 0.f, u_cur = 0.f;           // spine
    float hown0 = 0.f, hown1 = 0.f, bo0 = 0.f, bo1 = 0.f, bo2 = 0.f, bo3 = 0.f;

    if (cw == 0) {
        mu_own = mu0[b * 32u + lane];
        ep_cur = eps_g[(b * TLEN) * 32u + lane];
        u_cur  = (lane < 8) ? u_f[(b * TLEN) * 8u + lane] : 0.f;
    } else {
        hown0 = h0[b*64u + lane]; hown1 = h0[b*64u + 32 + lane];
        bo0 = bo[0]; bo1 = bo[1]; bo2 = bo[2]; bo3 = bo[3];
    }
    __syncthreads();
    if (cw == 0) {
        float a[32];
#pragma unroll
        for (int i = 0; i < 8; ++i) {
            float4 v = *(const float4*)(Sig0 + b * 1024u + (unsigned)(lane * 32 + 4 * i));
            a[4*i] = v.x; a[4*i+1] = v.y; a[4*i+2] = v.z; a[4*i+3] = v.w;
        }
        chol_init(a, lane, C.Ls);
    }
    __syncthreads();

#pragma unroll 1
    for (int t = 0; t < TLEN; ++t) {
        const unsigned bt  = b * TLEN + (unsigned)t;
        const unsigned btn = bt + (t < TLEN - 1 ? 1u : 0u);
        float sregH[32];
        u64 gha01 = 0, gha23 = 0, gha45 = 0;
        float mu_new = 0.f, ep_nxt = 0.f, u_nxt = 0.f;

        // ===== P01: each warp computes its own A-mixture =======================
        if (cw == 0) {
            ep_nxt = eps_g[btn * 32u + lane];
            u_nxt  = (lane < 8) ? u_f[btn * 8u + lane] : 0.f;
            float ar[32];
#pragma unroll
            for (int k = 0; k < 32; ++k)
                ar[k] = mix4(sh.w.AmT[k * 32 + lane], al0, al1, al2, al3);
            float m0 = 0.f, m1 = 0.f;
#pragma unroll
            for (int k = 0; k < 32; k += 2) {
                m0 = fmaf(ar[k],     __shfl_sync(FULLMASK, mu_own, k),     m0);
                m1 = fmaf(ar[k + 1], __shfl_sync(FULLMASK, mu_own, k + 1), m1);
            }
#pragma unroll
            for (int j = 0; j < 8; ++j) {
                float bj = mix4(sh.w.BmT[j * 32 + lane], al0, al1, al2, al3);
                m0 = fmaf(bj, __shfl_sync(FULLMASK, u_cur, j), m0);
            }
            mu_new = m0 + m1;
            out[OFF_MU + bt * 32u + lane] = mu_new;
#pragma unroll
            for (int i = 0; i < 8; ++i)
                *(float4*)(out + OFF_AT + bt * 1024u + (unsigned)(lane * 32 + 4 * i)) =
                    make_float4(ar[4*i], ar[4*i+1], ar[4*i+2], ar[4*i+3]);
            // G cols 16..31 (triangular), packed f32x2
            u64 gp[8];
#pragma unroll
            for (int i = 0; i < 8; ++i) gp[i] = 0ULL;
#pragma unroll
            for (int k = 16; k < 32; ++k) {
                u64 ak2 = pack2(ar[k], ar[k]);
                const int jbmax = (k - 16) >> 2;
#pragma unroll
                for (int jb = 0; jb < 4; ++jb) {
                    if (jb <= jbmax) {
                        ulonglong2 lv = *(const ulonglong2*)&C.Ls[k * 36 + 16 + 4 * jb];
                        gp[2*jb]   = ffma2(ak2, lv.x, gp[2*jb]);
                        gp[2*jb+1] = ffma2(ak2, lv.y, gp[2*jb+1]);
                    }
                }
            }
#pragma unroll
            for (int i = 0; i < 4; ++i) {
                float g0, g1, g2, g3;
                unpack2(gp[2*i], g0, g1); unpack2(gp[2*i+1], g2, g3);
                *(float4*)&C.Gs[lane * 36 + 16 + 4 * i] = make_float4(g0, g1, g2, g3);
            }
            __syncwarp();
            // S-high partial + Q fold, packed
#pragma unroll
            for (int j = 0; j < 32; ++j) {
                const ulonglong2* Gr = (const ulonglong2*)&C.Gs[j * 36 + 16];
                u64 acc01 = pack2(sh.w.QT[j * 32 + lane], 0.f);
                u64 acc23 = 0ULL;
#pragma unroll
                for (int i = 0; i < 4; ++i) {
                    ulonglong2 gv = Gr[i];
                    acc01 = ffma2(gp[2*i],   gv.x, acc01);
                    acc23 = ffma2(gp[2*i+1], gv.y, acc23);
                }
                float a0, a1, a2, a3;
                unpack2(acc01, a0, a1); unpack2(acc23, a2, a3);
                sregH[j] = (a0 + a1) + (a2 + a3);
            }
        } else {
#pragma unroll
            for (int e = 0; e < 16; ++e) {
                float cv = mix4(sh.w.CmS[e * 32 + lane], al0, al1, al2, al3);
                C.Cts[lane * 17 + e] = cv;
                out[OFF_CT + bt * 512u + (unsigned)(e * 32 + lane)] = cv;
            }
#pragma unroll
            for (int e = 0; e < 8; ++e)
                out[OFF_BT + bt * 256u + (unsigned)(e * 32 + lane)] =
                    mix4(sh.w.BmS[e * 32 + lane], al0, al1, al2, al3);
            float ar2[32];
#pragma unroll
            for (int k = 0; k < 32; ++k)
                ar2[k] = mix4(sh.w.AmT[k * 32 + lane], al0, al1, al2, al3);
            // G cols 0..15 (triangular), packed
            u64 gp[8];
#pragma unroll
            for (int i = 0; i < 8; ++i) gp[i] = 0ULL;
#pragma unroll
            for (int k = 0; k < 32; ++k) {
                u64 ak2 = pack2(ar2[k], ar2[k]);
                const int jbmax = (k >> 2) < 3 ? (k >> 2) : 3;
#pragma unroll
                for (int jb = 0; jb < 4; ++jb) {
                    if (jb <= jbmax) {
                        ulonglong2 lv = *(const ulonglong2*)&C.Ls[k * 36 + 4 * jb];
                        gp[2*jb]   = ffma2(ak2, lv.x, gp[2*jb]);
                        gp[2*jb+1] = ffma2(ak2, lv.y, gp[2*jb+1]);
                    }
                }
            }
#pragma unroll
            for (int i = 0; i < 4; ++i) {
                float g0, g1, g2, g3;
                unpack2(gp[2*i], g0, g1); unpack2(gp[2*i+1], g2, g3);
                *(float4*)&C.Gs[lane * 36 + 4 * i] = make_float4(g0, g1, g2, g3);
            }
            __syncwarp();
#pragma unroll
            for (int j = 0; j < 32; ++j) {
                const ulonglong2* Gr = (const ulonglong2*)&C.Gs[j * 36];
                u64 acc01 = 0ULL, acc23 = 0ULL;
#pragma unroll
                for (int i = 0; i < 4; ++i) {
                    ulonglong2 gv = Gr[i];
                    acc01 = ffma2(gp[2*i],   gv.x, acc01);
                    acc23 = ffma2(gp[2*i+1], gv.y, acc23);
                }
                float a0, a1, a2, a3;
                unpack2(acc01, a0, a1); unpack2(acc23, a2, a3);
                sregH[j] = (a0 + a1) + (a2 + a3);
            }
#pragma unroll
            for (int i = 0; i < 8; ++i)
                *(float4*)&C.Ss1[lane * 36 + 4 * i] =
                    make_float4(sregH[4*i], sregH[4*i+1], sregH[4*i+2], sregH[4*i+3]);
        }
        CBAR();

        // ===== P2: spine assemble + SsF + FUSED chol(z,gx,a_t); helper gh =====
        if (cw == 0) {
#pragma unroll
            for (int i = 0; i < 8; ++i) {
                float4 v = *(const float4*)&C.Ss1[lane * 36 + 4 * i];
                sregH[4*i+0] += v.x; sregH[4*i+1] += v.y;
                sregH[4*i+2] += v.z; sregH[4*i+3] += v.w;
            }
#pragma unroll
            for (int i = 0; i < 8; ++i)        // assembled S -> smem (helper stores)
                *(float4*)&C.SsF[lane * 36 + 4 * i] =
                    make_float4(sregH[4*i], sregH[4*i+1], sregH[4*i+2], sregH[4*i+3]);

            // fused Cholesky: z, gx (f32x2), a_t in the d-chain shadows
            float zacc = mu_new;
            u64 gxa01 = pack2(sh.w.bxs[lane],       sh.w.bxs[lane + 32]);
            u64 gxa23 = pack2(sh.w.bxs[lane + 64],  sh.w.bxs[lane + 96]);
            u64 gxa45 = pack2(sh.w.bxs[lane + 128], sh.w.bxs[lane + 160]);
            float at_acc = 0.f;
            const int lr = lane & 15;
#pragma unroll
            for (int j = 0; j < 32; ++j) {
                float d   = __shfl_sync(FULLMASK, sregH[j], j);
                float rs  = rsqrtf(d);
                float lij = sregH[j] * rs;
                sregH[j] = lij;
                float ej = __shfl_sync(FULLMASK, ep_cur, j);
                if (lane >= j) zacc = fmaf(lij, ej, zacc);
                float zj = __shfl_sync(FULLMASK, zacc, j);   // final z[j]
                {
                    u64 zj2 = pack2(zj, zj);
                    ulonglong2 wv = *(const ulonglong2*)&sh.w.Wx4[j * 32 + lane];
                    u64 w2 = *(const u64*)&sh.w.Wx2[j * 32 + lane];
                    gxa01 = ffma2(zj2, wv.x, gxa01);
                    gxa23 = ffma2(zj2, wv.y, gxa23);
                    gxa45 = ffma2(zj2, w2,   gxa45);
                    at_acc = fmaf(C.Cts[j * 17 + lr], zj, at_acc);
                }
                float lsq = lij * lij;
#pragma unroll
                for (int k = j + 1; k < 32; ++k) {
                    float lkj = __shfl_sync(FULLMASK, lij, k);
                    if (k == lane) sregH[k] -= lsq;
                    else           sregH[k] = fmaf(-lij, lkj, sregH[k]);
                }
            }
#pragma unroll
            for (int k = 0; k < 32; ++k) if (k > lane) sregH[k] = 0.f;
#pragma unroll
            for (int i = 0; i < 8; ++i)
                *(float4*)&C.Ls[lane * 36 + 4 * i] =
                    make_float4(sregH[4*i], sregH[4*i+1], sregH[4*i+2], sregH[4*i+3]);

            out[OFF_Z + bt * 32u + lane] = zacc;
            if (lane < 16) out[OFF_A + bt * 16u + lane] = at_acc;
            {
                float x0, x1, x2, x3, x4, x5;
                unpack2(gxa01, x0, x1); unpack2(gxa23, x2, x3); unpack2(gxa45, x4, x5);
                C.gxs[lane]       = x0; C.gxs[lane + 32]  = x1;
                C.gxs[lane + 64]  = x2; C.gxs[lane + 96]  = x3;
                C.gxs[lane + 128] = x4; C.gxs[lane + 160] = x5;
            }
            mu_own = mu_new; ep_cur = ep_nxt; u_cur = u_nxt;
        } else {
            gha01 = pack2(sh.w.bhs[lane],       sh.w.bhs[lane + 32]);
            gha23 = pack2(sh.w.bhs[lane + 64],  sh.w.bhs[lane + 96]);
            gha45 = pack2(sh.w.bhs[lane + 128], sh.w.bhs[lane + 160]);
#pragma unroll 4
            for (int hh = 0; hh < 32; ++hh) {
                float hv = __shfl_sync(FULLMASK, hown0, hh);
                u64 hv2 = pack2(hv, hv);
                ulonglong2 wv = *(const ulonglong2*)&sh.w.Wh4[hh * 32 + lane];
                u64 w2 = *(const u64*)&sh.w.Wh2[hh * 32 + lane];
                gha01 = ffma2(hv2, wv.x, gha01);
                gha23 = ffma2(hv2, wv.y, gha23);
                gha45 = ffma2(hv2, w2,   gha45);
            }
#pragma unroll 4
            for (int hh = 0; hh < 32; ++hh) {
                float hv = __shfl_sync(FULLMASK, hown1, hh);
                u64 hv2 = pack2(hv, hv);
                ulonglong2 wv = *(const ulonglong2*)&sh.w.Wh4[(hh + 32) * 32 + lane];
                u64 w2 = *(const u64*)&sh.w.Wh2[(hh + 32) * 32 + lane];
                gha01 = ffma2(hv2, wv.x, gha01);
                gha23 = ffma2(hv2, wv.y, gha23);
                gha45 = ffma2(hv2, w2,   gha45);
            }
        }
        CBAR();

        // ===== P3: helper Sigma out + GRU + softmax ============================
        if (cw == 1) {
#pragma unroll
            for (int i = 0; i < 8; ++i) {
                float4 v = *(const float4*)&C.SsF[lane * 36 + 4 * i];
                *(float4*)(out + OFF_SIG + bt * 1024u + (unsigned)(lane * 32 + 4 * i)) = v;
            }
            float gh0, gh1, gh2, gh3, gh4, gh5;
            unpack2(gha01, gh0, gh1); unpack2(gha23, gh2, gh3); unpack2(gha45, gh4, gh5);
            float gx0 = C.gxs[lane],       gx1 = C.gxs[lane + 32];
            float gx2 = C.gxs[lane + 64],  gx3 = C.gxs[lane + 96];
            float gx4 = C.gxs[lane + 128], gx5 = C.gxs[lane + 160];
            float r0 = fast_sigmoid(gx0 + gh0);
            float r1 = fast_sigmoid(gx1 + gh1);
            float zg0 = fast_sigmoid(gx2 + gh2);
            float zg1 = fast_sigmoid(gx3 + gh3);
            float n0 = fast_tanh(gx4 + r0 * gh4);
            float n1 = fast_tanh(gx5 + r1 * gh5);
            hown0 = (1.f - zg0) * n0 + zg0 * hown0;
            hown1 = (1.f - zg1) * n1 + zg1 * hown1;
            float4 w0 = sh.w.Wo4[lane], w1 = sh.w.Wo4[lane + 32];
            float p0 = fmaf(hown0, w0.x, hown1 * w1.x);
            float p1 = fmaf(hown0, w0.y, hown1 * w1.y);
            float p2 = fmaf(hown0, w0.z, hown1 * w1.z);
            float p3 = fmaf(hown0, w0.w, hown1 * w1.w);
#pragma unroll
            for (int off = 16; off; off >>= 1) {
                p0 += __shfl_xor_sync(FULLMASK, p0, off);
                p1 += __shfl_xor_sync(FULLMASK, p1, off);
                p2 += __shfl_xor_sync(FULLMASK, p2, off);
                p3 += __shfl_xor_sync(FULLMASK, p3, off);
            }
            float o0 = p0 + bo0, o1 = p1 + bo1, o2 = p2 + bo2, o3 = p3 + bo3;
            float mx = fmaxf(fmaxf(o0, o1), fmaxf(o2, o3));
            float e0 = __expf(o0 - mx), e1 = __expf(o1 - mx);
            float e2 = __expf(o2 - mx), e3 = __expf(o3 - mx);
            float inv = 1.f / (e0 + e1 + e2 + e3);
            if (lane == 0) {
                C.alsh[0] = e0 * inv; C.alsh[1] = e1 * inv;
                C.alsh[2] = e2 * inv; C.alsh[3] = e3 * inv;
            }
        }
        CBAR();
        al0 = C.alsh[0]; al1 = C.alsh[1]; al2 = C.alsh[2]; al3 = C.alsh[3];
    }
#undef CBAR
}

extern "C" void kernel_launch(void* const* d_in, const int* in_sizes, int n_in,
                              void* d_out, int out_size)
{
    size_t shbytes = sizeof(SAll);
    cudaFuncSetAttribute(lgssm_kernel,
                         cudaFuncAttributeMaxDynamicSharedMemorySize, (int)shbytes);
    lgssm_kernel<<<128, 128, shbytes>>>(
        (const float*)d_in[0],  (const float*)d_in[1],  (const float*)d_in[2],
        (const float*)d_in[3],  (const float*)d_in[4],  (const float*)d_in[5],
        (const float*)d_in[6],  (const float*)d_in[7],  (const float*)d_in[8],
        (const float*)d_in[9],  (const float*)d_in[10], (const float*)d_in[11],
        (const float*)d_in[12], (const float*)d_in[13], (const float*)d_in[14],
        (const float*)d_in[15], (float*)d_out);
}